// round 14
// baseline (speedup 1.0000x reference)
#include <cuda_runtime.h>
#include <cuda_bf16.h>
#include <math.h>
#include <stdint.h>

// Problem constants
#define Bb 32
#define Ss 512
#define Dd 1024
#define Hh 16
#define Ff 4096
#define Mm (Bb*Ss)   // 16384

// ---------------- scratch (device globals; no allocation) ----------------
__device__ float g_q  [(size_t)Mm*Dd];
__device__ float g_k  [(size_t)Mm*Dd];
__device__ float g_v  [(size_t)Mm*Dd];
__device__ float g_vt [(size_t)Bb*Hh*64*Ss];
__device__ float g_ctx[(size_t)Mm*Dd];
__device__ float g_t1 [(size_t)Mm*Dd];
__device__ float g_o1 [(size_t)Mm*Dd];
__device__ float g_ffn[(size_t)Mm*Ff];
// transposed (K-major, tf32-rounded) weights
__device__ float g_wqt[(size_t)Dd*Dd];
__device__ float g_wkt[(size_t)Dd*Dd];
__device__ float g_wvt[(size_t)Dd*Dd];
__device__ float g_wot[(size_t)Dd*Dd];
__device__ float g_w1t[(size_t)Dd*Ff];
__device__ float g_w2t[(size_t)Dd*Ff];

// ---------------- helpers ----------------
__device__ __forceinline__ uint32_t smem_u32(const void* p) {
    uint32_t a;
    asm("{ .reg .u64 t; cvta.to.shared.u64 t, %1; cvt.u32.u64 %0, t; }" : "=r"(a) : "l"(p));
    return a;
}
__device__ __forceinline__ float rn_tf32(float x) {
    float r;
    asm("cvt.rna.tf32.f32 %0, %1;" : "=f"(r) : "f"(x));
    return r;
}
__device__ __forceinline__ void cp16(uint32_t dst, const void* src) {
    asm volatile("cp.async.cg.shared.global [%0], [%1], 16;" :: "r"(dst), "l"(src));
}
#define CP_COMMIT() asm volatile("cp.async.commit_group;" ::: "memory")

__device__ __forceinline__ void ldsm_x4(uint32_t& r0, uint32_t& r1, uint32_t& r2, uint32_t& r3,
                                        uint32_t addr) {
    asm volatile("ldmatrix.sync.aligned.m8n8.x4.shared.b16 {%0,%1,%2,%3}, [%4];"
                 : "=r"(r0), "=r"(r1), "=r"(r2), "=r"(r3) : "r"(addr));
}
__device__ __forceinline__ void ldsm_x2(uint32_t& r0, uint32_t& r1, uint32_t addr) {
    asm volatile("ldmatrix.sync.aligned.m8n8.x2.shared.b16 {%0,%1}, [%2];"
                 : "=r"(r0), "=r"(r1) : "r"(addr));
}

__device__ __forceinline__ void mma_tf32(float& c0, float& c1, float& c2, float& c3,
                                         uint32_t a0, uint32_t a1, uint32_t a2, uint32_t a3,
                                         uint32_t b0, uint32_t b1) {
    asm volatile(
        "mma.sync.aligned.m16n8k8.row.col.f32.tf32.tf32.f32 "
        "{%0,%1,%2,%3}, {%4,%5,%6,%7}, {%8,%9}, {%0,%1,%2,%3};"
        : "+f"(c0), "+f"(c1), "+f"(c2), "+f"(c3)
        : "r"(a0), "r"(a1), "r"(a2), "r"(a3), "r"(b0), "r"(b1));
}

// swizzled smem index for a [rows x 32] fp32 tile: idx = row*32 + (col ^ ((row&7)<<2))
__device__ __forceinline__ int swz(int row, int col) {
    return row * 32 + (col ^ ((row & 7) << 2));
}

// ---------------- mma.sync tf32 GEMM: C = A[MxK] @ Bt[NxK]^T + bias ----
// ACT: 0 = none, 1 = GELU, 2 = tf32-round output
// 128x256 CTA tile, BK=32, 256 threads (8 warps, 2x4), warp tile 64x64.
// Double-buffered cp.async; ldmatrix fragment loads.
// smem: per buffer A 128x32 (4096 fl) + B 256x32 (8192 fl) = 12288 fl; 2 buffers.
#define GSM_BYTES (2 * 12288 * 4)

template<int ACT>
__global__ __launch_bounds__(256)
void gemm_tc(const float* __restrict__ A, const float* __restrict__ Bt,
             const float* __restrict__ bias, float* __restrict__ C,
             int M_, int N_, int K_) {
    extern __shared__ float smf[];
    const uint32_t smb = smem_u32(smf);

    const int tid = threadIdx.x, w = tid >> 5, lane = tid & 31;
    const int wm = w >> 2, wn = w & 3;
    const int g = lane >> 2, tg = lane & 3;
    const int row0 = blockIdx.y * 128, col0 = blockIdx.x * 256;

    const uint32_t X = (uint32_t)((lane & 7) << 2);
    const uint32_t aRow = (uint32_t)(wm * 64 + (lane & 15)) * 128;            // bytes
    const uint32_t aCb  = (uint32_t)((lane >> 4) << 2);                       // floats
    // B ldsm_x4: matrices (nn, klo),(nn, khi),(nn+4, klo),(nn+4, khi)
    const uint32_t bRow = (uint32_t)(wn * 64 + ((lane >> 4) << 5) + (lane & 7)) * 128;
    const uint32_t bCb  = (uint32_t)(((lane >> 3) & 1) << 2);

    float acc[4][8][4];
#pragma unroll
    for (int mi = 0; mi < 4; mi++)
#pragma unroll
        for (int ni = 0; ni < 8; ni++)
#pragma unroll
            for (int c = 0; c < 4; c++) acc[mi][ni][c] = 0.f;

    const int T = K_ >> 5;

    auto load_tile = [&](int t, int buf) {
        const int k0g = t << 5;
        const uint32_t ab = smb + (uint32_t)buf * 49152u;
        const uint32_t bb = ab + 16384u;
#pragma unroll
        for (int it = 0; it < 4; it++) {
            int idx = it * 256 + tid;
            int r = idx >> 3, j = idx & 7;
            cp16(ab + (uint32_t)swz(r, j * 4) * 4, &A[(size_t)(row0 + r) * K_ + k0g + j * 4]);
        }
#pragma unroll
        for (int it = 0; it < 8; it++) {
            int idx = it * 256 + tid;
            int r = idx >> 3, j = idx & 7;
            cp16(bb + (uint32_t)swz(r, j * 4) * 4, &Bt[(size_t)(col0 + r) * K_ + k0g + j * 4]);
        }
        CP_COMMIT();
    };

    load_tile(0, 0);

    for (int t = 0; t < T; t++) {
        if (t + 1 < T) {
            load_tile(t + 1, (t + 1) & 1);
            asm volatile("cp.async.wait_group 1;" ::: "memory");
        } else {
            asm volatile("cp.async.wait_group 0;" ::: "memory");
        }
        __syncthreads();

        const uint32_t abuf = smb + (uint32_t)(t & 1) * 49152u;
        const uint32_t bbuf = abuf + 16384u;

#pragma unroll
        for (int ks = 0; ks < 4; ks++) {
            const uint32_t k0 = (uint32_t)(ks * 8);
            const uint32_t aoff = (((k0 + aCb) ^ X) << 2);
            const uint32_t boff = (((k0 + bCb) ^ X) << 2);
            uint32_t af[4][4];
#pragma unroll
            for (int mi = 0; mi < 4; mi++)
                ldsm_x4(af[mi][0], af[mi][1], af[mi][2], af[mi][3],
                        abuf + aRow + (uint32_t)(mi * 2048) + aoff);
            uint32_t bf[8][2];
#pragma unroll
            for (int nn = 0; nn < 4; nn++)
                ldsm_x4(bf[nn][0], bf[nn][1], bf[nn + 4][0], bf[nn + 4][1],
                        bbuf + bRow + (uint32_t)(nn * 1024) + boff);
#pragma unroll
            for (int mi = 0; mi < 4; mi++)
#pragma unroll
                for (int q = 0; q < 4; q++)
                    af[mi][q] = __float_as_uint(rn_tf32(__uint_as_float(af[mi][q])));
#pragma unroll
            for (int mi = 0; mi < 4; mi++)
#pragma unroll
                for (int ni = 0; ni < 8; ni++)
                    mma_tf32(acc[mi][ni][0], acc[mi][ni][1], acc[mi][ni][2], acc[mi][ni][3],
                             af[mi][0], af[mi][1], af[mi][2], af[mi][3],
                             bf[ni][0], bf[ni][1]);
        }
        __syncthreads();
    }

#pragma unroll
    for (int mi = 0; mi < 4; mi++) {
#pragma unroll
        for (int ni = 0; ni < 8; ni++) {
            int row = row0 + wm * 64 + mi * 16 + g;
            int col = col0 + wn * 64 + ni * 8 + tg * 2;
            float b0 = bias[col], b1 = bias[col + 1];
#pragma unroll
            for (int hh = 0; hh < 2; hh++) {
                int r = row + hh * 8;
                float o0 = acc[mi][ni][hh * 2 + 0] + b0;
                float o1 = acc[mi][ni][hh * 2 + 1] + b1;
                if (ACT == 1) {
                    o0 = 0.5f * o0 * (1.f + erff(o0 * 0.70710678118654752440f));
                    o1 = 0.5f * o1 * (1.f + erff(o1 * 0.70710678118654752440f));
                }
                if (ACT == 2) { o0 = rn_tf32(o0); o1 = rn_tf32(o1); }
                float2 o = make_float2(o0, o1);
                *(float2*)&C[(size_t)r * N_ + col] = o;
            }
        }
    }
}

// ---------------- transpose + tf32-round: Wt[n][k] = rn(W[k][n]) ----------------
__global__ __launch_bounds__(256)
void transpose_rn(const float* __restrict__ W, float* __restrict__ Wt, int Kd, int Nd) {
    __shared__ float t[32][33];
    const int n0 = blockIdx.x * 32, k0 = blockIdx.y * 32;
    const int tx = threadIdx.x & 31, ty = (threadIdx.x >> 5) * 4;
#pragma unroll
    for (int i = 0; i < 4; i++)
        t[ty + i][tx] = W[(size_t)(k0 + ty + i) * Nd + n0 + tx];
    __syncthreads();
#pragma unroll
    for (int i = 0; i < 4; i++)
        Wt[(size_t)(n0 + ty + i) * Kd + k0 + tx] = rn_tf32(t[tx][ty + i]);
}

// ---------------- per-head V transpose: Vt[bh][dk][s] = V[b*S+s][h*64+dk] ----
__global__ __launch_bounds__(256)
void transpose_v(const float* __restrict__ V, float* __restrict__ Vt) {
    __shared__ float t[32][33];
    const int bh = blockIdx.z, b = bh >> 4, h = bh & 15;
    const int s0 = blockIdx.x * 32, d0 = blockIdx.y * 32;
    const int tx = threadIdx.x & 31, ty = (threadIdx.x >> 5) * 4;
#pragma unroll
    for (int i = 0; i < 4; i++)
        t[ty + i][tx] = V[(size_t)(b * Ss + s0 + ty + i) * Dd + h * 64 + d0 + tx];
    __syncthreads();
#pragma unroll
    for (int i = 0; i < 4; i++)
        Vt[((size_t)bh * 64 + d0 + ty + i) * Ss + s0 + tx] = t[tx][ty + i];
}

// ---------------- mma flash attention ----------------
// grid (B*H, S/128), 256 threads, 8 warps x 16 q-rows. K/V chunks of 64.
#define ATT_SM_BYTES (32768 * 4)

__global__ __launch_bounds__(256)
void attn_mma(const float* __restrict__ Q, const float* __restrict__ Kg,
              const float* __restrict__ Vt, const int* __restrict__ mask,
              const float* __restrict__ adj, float* __restrict__ Octx) {
    extern __shared__ float sa[];
    const uint32_t smb = smem_u32(sa);
    const int tid = threadIdx.x, w = tid >> 5, lane = tid & 31;
    const int bh = blockIdx.x, b = bh >> 4, h = bh & 15;
    const int q0 = blockIdx.y << 7;
    const int wq = w << 4;
    const int g = lane >> 2, tg = lane & 3;

    const uint32_t Ko[2] = {8192, 12288}, Vo[2] = {16384, 20480};
    const uint32_t Po = 24576 + (uint32_t)w * 1024;

    const uint32_t X   = (uint32_t)((lane & 7) << 2);
    const uint32_t aCb = (uint32_t)((lane >> 4) << 2);
    const uint32_t bCb = (uint32_t)(((lane >> 3) & 1) << 2);

    // Q tile [128 x 64] -> smem (swizzled)
#pragma unroll
    for (int it = 0; it < 8; it++) {
        int idx = it * 256 + tid;
        int r = idx >> 4, j = idx & 15;
        uint32_t doff = (uint32_t)(r * 64 + ((j * 4) ^ ((r & 7) << 2))) * 4;
        cp16(smb + doff, &Q[(size_t)(b * Ss + q0 + r) * Dd + h * 64 + j * 4]);
    }
    CP_COMMIT();

    auto load_kv = [&](int c, int buf) {
        const uint32_t kb = smb + Ko[buf] * 4;
        const uint32_t vb = smb + Vo[buf] * 4;
        const int kc = c << 6;
#pragma unroll
        for (int it = 0; it < 4; it++) {
            int idx = it * 256 + tid;
            int r = idx >> 4, j = idx & 15;
            uint32_t doff = (uint32_t)(r * 64 + ((j * 4) ^ ((r & 7) << 2))) * 4;
            cp16(kb + doff, &Kg[(size_t)(b * Ss + kc + r) * Dd + h * 64 + j * 4]);
            cp16(vb + doff, &Vt[((size_t)bh * 64 + r) * Ss + kc + j * 4]);
        }
        CP_COMMIT();
    };
    load_kv(0, 0);

    asm volatile("cp.async.wait_group 1;" ::: "memory");   // Q ready
    __syncthreads();

    // Q fragments (pre-rounded tf32 in the producing GEMM)
    uint32_t aq[8][4];
    {
        uint32_t qrow = smb + (uint32_t)(wq + (lane & 15)) * 256;
#pragma unroll
        for (int ks = 0; ks < 8; ks++)
            ldsm_x4(aq[ks][0], aq[ks][1], aq[ks][2], aq[ks][3],
                    qrow + ((((uint32_t)(ks * 8) + aCb) ^ X) << 2));
    }

    float m0 = -3.0e38f, m1 = -3.0e38f, l0 = 0.f, l1 = 0.f;
    float ao[8][4];
#pragma unroll
    for (int n = 0; n < 8; n++)
#pragma unroll
        for (int c = 0; c < 4; c++) ao[n][c] = 0.f;

    const float* adj0 = adj + ((size_t)(b * Ss + q0 + wq + g)) * Ss + 2 * tg;
    const int*   mb0  = mask + b * Ss + 2 * tg;

    for (int t = 0; t < 8; t++) {
        if (t + 1 < 8) {
            load_kv(t + 1, (t + 1) & 1);
            asm volatile("cp.async.wait_group 1;" ::: "memory");
        } else {
            asm volatile("cp.async.wait_group 0;" ::: "memory");
        }
        __syncthreads();

        const uint32_t kb = smb + Ko[t & 1] * 4;
        const uint32_t vb = smb + Vo[t & 1] * 4;

        // S = Q @ K^T
        float s[8][4];
#pragma unroll
        for (int n = 0; n < 8; n++)
#pragma unroll
            for (int c = 0; c < 4; c++) s[n][c] = 0.f;
#pragma unroll
        for (int ks = 0; ks < 8; ks++) {
            const uint32_t coff = ((((uint32_t)(ks * 8) + bCb) ^ X) << 2);
#pragma unroll
            for (int n = 0; n < 8; n++) {
                uint32_t b0, b1;
                ldsm_x2(b0, b1, kb + (uint32_t)(n * 8 + (lane & 7)) * 256 + coff);
                mma_tf32(s[n][0], s[n][1], s[n][2], s[n][3],
                         aq[ks][0], aq[ks][1], aq[ks][2], aq[ks][3], b0, b1);
            }
        }

        // mask + adj + scale; row max
        const int kc = t << 6;
        float mx0 = -3.0e38f, mx1 = -3.0e38f;
#pragma unroll
        for (int n = 0; n < 8; n++) {
            float2 a0 = *(const float2*)(adj0 + kc + n * 8);
            float2 a1 = *(const float2*)(adj0 + 8 * Ss + kc + n * 8);
            int2   mk = *(const int2*)  (mb0 + kc + n * 8);
            float p0 = (float)mk.x * -1e9f, p1 = (float)mk.y * -1e9f;
            s[n][0] = s[n][0] * 0.125f + p0 + a0.x;
            s[n][1] = s[n][1] * 0.125f + p1 + a0.y;
            s[n][2] = s[n][2] * 0.125f + p0 + a1.x;
            s[n][3] = s[n][3] * 0.125f + p1 + a1.y;
            mx0 = fmaxf(mx0, fmaxf(s[n][0], s[n][1]));
            mx1 = fmaxf(mx1, fmaxf(s[n][2], s[n][3]));
        }
        mx0 = fmaxf(mx0, __shfl_xor_sync(0xffffffffu, mx0, 1));
        mx0 = fmaxf(mx0, __shfl_xor_sync(0xffffffffu, mx0, 2));
        mx1 = fmaxf(mx1, __shfl_xor_sync(0xffffffffu, mx1, 1));
        mx1 = fmaxf(mx1, __shfl_xor_sync(0xffffffffu, mx1, 2));

        float mn0 = fmaxf(m0, mx0), mn1 = fmaxf(m1, mx1);
        float cor0 = expf(m0 - mn0), cor1 = expf(m1 - mn1);

        float ps0 = 0.f, ps1 = 0.f;
        const uint32_t xs = (uint32_t)(g << 2);
        float* Pw = sa + Po;
#pragma unroll
        for (int n = 0; n < 8; n++) {
            float p0 = rn_tf32(expf(s[n][0] - mn0));
            float p1 = rn_tf32(expf(s[n][1] - mn0));
            float p2 = rn_tf32(expf(s[n][2] - mn1));
            float p3 = rn_tf32(expf(s[n][3] - mn1));
            ps0 += p0 + p1; ps1 += p2 + p3;
            uint32_t cidx = ((uint32_t)(n * 8 + 2 * tg)) ^ xs;
            *(float2*)(Pw + g * 64 + cidx)       = make_float2(p0, p1);
            *(float2*)(Pw + (g + 8) * 64 + cidx) = make_float2(p2, p3);
        }
        ps0 += __shfl_xor_sync(0xffffffffu, ps0, 1);
        ps0 += __shfl_xor_sync(0xffffffffu, ps0, 2);
        ps1 += __shfl_xor_sync(0xffffffffu, ps1, 1);
        ps1 += __shfl_xor_sync(0xffffffffu, ps1, 2);
        l0 = l0 * cor0 + ps0; l1 = l1 * cor1 + ps1;
        m0 = mn0; m1 = mn1;
#pragma unroll
        for (int n = 0; n < 8; n++) {
            ao[n][0] *= cor0; ao[n][1] *= cor0;
            ao[n][2] *= cor1; ao[n][3] *= cor1;
        }
        __syncwarp();

        // O += P @ V   (Vt tile is [dk][key])
        const uint32_t prow = smb + Po * 4 + (uint32_t)(lane & 15) * 256;
#pragma unroll
        for (int ks = 0; ks < 8; ks++) {
            uint32_t ap0, ap1, ap2, ap3;
            ldsm_x4(ap0, ap1, ap2, ap3, prow + ((((uint32_t)(ks * 8) + aCb) ^ X) << 2));
            const uint32_t coff = ((((uint32_t)(ks * 8) + bCb) ^ X) << 2);
#pragma unroll
            for (int n = 0; n < 8; n++) {
                uint32_t b0, b1;
                ldsm_x2(b0, b1, vb + (uint32_t)(n * 8 + (lane & 7)) * 256 + coff);
                mma_tf32(ao[n][0], ao[n][1], ao[n][2], ao[n][3],
                         ap0, ap1, ap2, ap3, b0, b1);
            }
        }
        __syncthreads();
    }

    // epilogue
    const float inv0 = 1.0f / l0, inv1 = 1.0f / l1;
    const int qa = q0 + wq + g;
#pragma unroll
    for (int n = 0; n < 8; n++) {
        int col = h * 64 + n * 8 + 2 * tg;
        *(float2*)&Octx[(size_t)(b * Ss + qa) * Dd + col] =
            make_float2(ao[n][0] * inv0, ao[n][1] * inv0);
        *(float2*)&Octx[(size_t)(b * Ss + qa + 8) * Dd + col] =
            make_float2(ao[n][2] * inv1, ao[n][3] * inv1);
    }
}

// ---------------- fused residual add + LayerNorm (ddof=1, /(std+eps)) -------
__global__ __launch_bounds__(256)
void add_ln_kernel(const float* __restrict__ A, const float* __restrict__ Bv,
                   const float* __restrict__ gamma, const float* __restrict__ beta,
                   float* __restrict__ out) {
    const int row = blockIdx.x;
    const int tid = threadIdx.x;
    const size_t base = (size_t)row * 1024 + tid * 4;

    float4 a = *(const float4*)(A + base);
    float4 b = *(const float4*)(Bv + base);
    float v0 = a.x + b.x, v1 = a.y + b.y, v2 = a.z + b.z, v3 = a.w + b.w;

    __shared__ float red[8];
    __shared__ float s_stat;

    float s = v0 + v1 + v2 + v3;
#pragma unroll
    for (int o = 16; o >= 1; o >>= 1) s += __shfl_xor_sync(0xffffffffu, s, o);
    if ((tid & 31) == 0) red[tid >> 5] = s;
    __syncthreads();
    if (tid == 0) {
        float t = 0.f;
#pragma unroll
        for (int i = 0; i < 8; i++) t += red[i];
        s_stat = t * (1.0f / 1024.0f);
    }
    __syncthreads();
    const float mean = s_stat;

    float d0 = v0 - mean, d1 = v1 - mean, d2 = v2 - mean, d3 = v3 - mean;
    float q = d0 * d0 + d1 * d1 + d2 * d2 + d3 * d3;
#pragma unroll
    for (int o = 16; o >= 1; o >>= 1) q += __shfl_xor_sync(0xffffffffu, q, o);
    if ((tid & 31) == 0) red[tid >> 5] = q;
    __syncthreads();
    if (tid == 0) {
        float t = 0.f;
#pragma unroll
        for (int i = 0; i < 8; i++) t += red[i];
        float var = t * (1.0f / 1023.0f);        // ddof = 1
        s_stat = 1.0f / (sqrtf(var) + 1e-6f);    // 1 / (std + eps)
    }
    __syncthreads();
    const float rs = s_stat;

    float4 gm = *(const float4*)(gamma + tid * 4);
    float4 bt = *(const float4*)(beta  + tid * 4);
    float4 o;
    o.x = gm.x * d0 * rs + bt.x;
    o.y = gm.y * d1 * rs + bt.y;
    o.z = gm.z * d2 * rs + bt.z;
    o.w = gm.w * d3 * rs + bt.w;
    *(float4*)(out + base) = o;
}

// ---------------- launch ----------------
extern "C" void kernel_launch(void* const* d_in, const int* in_sizes, int n_in,
                              void* d_out, int out_size) {
    const float* x    = (const float*)d_in[0];
    const int*   mask = (const int*)  d_in[1];
    const float* adj  = (const float*)d_in[2];
    const float* Wq = (const float*)d_in[4],  *bq = (const float*)d_in[5];
    const float* Wk = (const float*)d_in[6],  *bk = (const float*)d_in[7];
    const float* Wv = (const float*)d_in[8],  *bv = (const float*)d_in[9];
    const float* Wo = (const float*)d_in[10], *bo = (const float*)d_in[11];
    const float* W1 = (const float*)d_in[12], *b1 = (const float*)d_in[13];
    const float* W2 = (const float*)d_in[14], *b2 = (const float*)d_in[15];
    const float* gamma = (const float*)d_in[16];
    const float* beta  = (const float*)d_in[17];
    float* out = (float*)d_out;

    float *q, *k, *v, *vt, *ctx, *t1, *o1, *ffn;
    float *wqt, *wkt, *wvt, *wot, *w1t, *w2t;
    cudaGetSymbolAddress((void**)&q,   g_q);
    cudaGetSymbolAddress((void**)&k,   g_k);
    cudaGetSymbolAddress((void**)&v,   g_v);
    cudaGetSymbolAddress((void**)&vt,  g_vt);
    cudaGetSymbolAddress((void**)&ctx, g_ctx);
    cudaGetSymbolAddress((void**)&t1,  g_t1);
    cudaGetSymbolAddress((void**)&o1,  g_o1);
    cudaGetSymbolAddress((void**)&ffn, g_ffn);
    cudaGetSymbolAddress((void**)&wqt, g_wqt);
    cudaGetSymbolAddress((void**)&wkt, g_wkt);
    cudaGetSymbolAddress((void**)&wvt, g_wvt);
    cudaGetSymbolAddress((void**)&wot, g_wot);
    cudaGetSymbolAddress((void**)&w1t, g_w1t);
    cudaGetSymbolAddress((void**)&w2t, g_w2t);

    cudaFuncSetAttribute(gemm_tc<0>, cudaFuncAttributeMaxDynamicSharedMemorySize, GSM_BYTES);
    cudaFuncSetAttribute(gemm_tc<1>, cudaFuncAttributeMaxDynamicSharedMemorySize, GSM_BYTES);
    cudaFuncSetAttribute(gemm_tc<2>, cudaFuncAttributeMaxDynamicSharedMemorySize, GSM_BYTES);
    cudaFuncSetAttribute(attn_mma, cudaFuncAttributeMaxDynamicSharedMemorySize, ATT_SM_BYTES);

    const dim3 blk(256);
    const dim3 tD(Dd / 32, Dd / 32);
    transpose_rn<<<tD, blk>>>(Wq, wqt, Dd, Dd);
    transpose_rn<<<tD, blk>>>(Wk, wkt, Dd, Dd);
    transpose_rn<<<tD, blk>>>(Wv, wvt, Dd, Dd);
    transpose_rn<<<tD, blk>>>(Wo, wot, Dd, Dd);
    transpose_rn<<<dim3(Ff / 32, Dd / 32), blk>>>(W1, w1t, Dd, Ff);
    transpose_rn<<<dim3(Dd / 32, Ff / 32), blk>>>(W2, w2t, Ff, Dd);

    const dim3 gD(Dd / 256, Mm / 128);   // (4, 128)
    const dim3 gF(Ff / 256, Mm / 128);   // (16, 128)

    // 1-3. Q/K/V projections (tf32-rounded outputs for the mma attention)
    gemm_tc<2><<<gD, blk, GSM_BYTES>>>(x, wqt, bq, q, Mm, Dd, Dd);
    gemm_tc<2><<<gD, blk, GSM_BYTES>>>(x, wkt, bk, k, Mm, Dd, Dd);
    gemm_tc<2><<<gD, blk, GSM_BYTES>>>(x, wvt, bv, v, Mm, Dd, Dd);

    // 3b. per-head V transpose
    transpose_v<<<dim3(Ss / 32, 2, Bb * Hh), blk>>>(v, vt);

    // 4. attention (tensor cores)
    attn_mma<<<dim3(Bb * Hh, Ss / 128), blk, ATT_SM_BYTES>>>(q, k, vt, mask, adj, ctx);

    // 5. output projection
    gemm_tc<0><<<gD, blk, GSM_BYTES>>>(ctx, wot, bo, t1, Mm, Dd, Dd);

    // 6. residual + LN -> out1
    add_ln_kernel<<<Mm, blk>>>(x, t1, gamma, beta, o1);

    // 7. FFN1 + GELU
    gemm_tc<1><<<gF, blk, GSM_BYTES>>>(o1, w1t, b1, ffn, Mm, Ff, Dd);

    // 8. FFN2
    gemm_tc<0><<<gD, blk, GSM_BYTES>>>(ffn, w2t, b2, t1, Mm, Dd, Ff);

    // 9. residual + LN -> out
    add_ln_kernel<<<Mm, blk>>>(o1, t1, gamma, beta, out);
}

// round 15
// speedup vs baseline: 1.0779x; 1.0779x over previous
#include <cuda_runtime.h>
#include <cuda_bf16.h>
#include <math.h>
#include <stdint.h>

// Problem constants
#define Bb 32
#define Ss 512
#define Dd 1024
#define Hh 16
#define Ff 4096
#define Mm (Bb*Ss)   // 16384

// ---------------- scratch (device globals; no allocation) ----------------
__device__ float g_q  [(size_t)Mm*Dd];
__device__ float g_k  [(size_t)Mm*Dd];
__device__ float g_v  [(size_t)Mm*Dd];
__device__ float g_vt [(size_t)Bb*Hh*64*Ss];
__device__ float g_ctx[(size_t)Mm*Dd];
__device__ float g_t1 [(size_t)Mm*Dd];
__device__ float g_o1 [(size_t)Mm*Dd];
__device__ float g_ffn[(size_t)Mm*Ff];
// transposed (K-major, tf32-rounded) weights
__device__ float g_wqt[(size_t)Dd*Dd];
__device__ float g_wkt[(size_t)Dd*Dd];
__device__ float g_wvt[(size_t)Dd*Dd];
__device__ float g_wot[(size_t)Dd*Dd];
__device__ float g_w1t[(size_t)Dd*Ff];
__device__ float g_w2t[(size_t)Dd*Ff];

// ---------------- helpers ----------------
__device__ __forceinline__ uint32_t smem_u32(const void* p) {
    uint32_t a;
    asm("{ .reg .u64 t; cvta.to.shared.u64 t, %1; cvt.u32.u64 %0, t; }" : "=r"(a) : "l"(p));
    return a;
}
__device__ __forceinline__ float rn_tf32(float x) {
    float r;
    asm("cvt.rna.tf32.f32 %0, %1;" : "=f"(r) : "f"(x));
    return r;
}
__device__ __forceinline__ void cp16(uint32_t dst, const void* src) {
    asm volatile("cp.async.cg.shared.global [%0], [%1], 16;" :: "r"(dst), "l"(src));
}
#define CP_COMMIT() asm volatile("cp.async.commit_group;" ::: "memory")

__device__ __forceinline__ void ldsm_x4(uint32_t& r0, uint32_t& r1, uint32_t& r2, uint32_t& r3,
                                        uint32_t addr) {
    asm volatile("ldmatrix.sync.aligned.m8n8.x4.shared.b16 {%0,%1,%2,%3}, [%4];"
                 : "=r"(r0), "=r"(r1), "=r"(r2), "=r"(r3) : "r"(addr));
}
__device__ __forceinline__ void ldsm_x2(uint32_t& r0, uint32_t& r1, uint32_t addr) {
    asm volatile("ldmatrix.sync.aligned.m8n8.x2.shared.b16 {%0,%1}, [%2];"
                 : "=r"(r0), "=r"(r1) : "r"(addr));
}

__device__ __forceinline__ void mma_tf32(float& c0, float& c1, float& c2, float& c3,
                                         uint32_t a0, uint32_t a1, uint32_t a2, uint32_t a3,
                                         uint32_t b0, uint32_t b1) {
    asm volatile(
        "mma.sync.aligned.m16n8k8.row.col.f32.tf32.tf32.f32 "
        "{%0,%1,%2,%3}, {%4,%5,%6,%7}, {%8,%9}, {%0,%1,%2,%3};"
        : "+f"(c0), "+f"(c1), "+f"(c2), "+f"(c3)
        : "r"(a0), "r"(a1), "r"(a2), "r"(a3), "r"(b0), "r"(b1));
}

// swizzled smem index for a [rows x 32] fp32 tile: idx = row*32 + (col ^ ((row&7)<<2))
__device__ __forceinline__ int swz(int row, int col) {
    return row * 32 + (col ^ ((row & 7) << 2));
}

// ---------------- mma.sync tf32 GEMM: C = A[MxK] @ Bt[NxK]^T + bias ----
// ACT: 0 = none, 1 = GELU, 2 = tf32-round output
// 128x128 CTA tile, BK=32, 256 threads (8 warps, 2x4), warp tile 64x32.
// THREE-stage cp.async pipeline; ldmatrix fragment loads.
// smem: 3 buffers x (A 128x32 + B 128x32) fp32 = 3 x 32 KB = 96 KB.
#define GSM_BYTES (3 * 32768)

template<int ACT>
__global__ __launch_bounds__(256, 2)
void gemm_tc(const float* __restrict__ A, const float* __restrict__ Bt,
             const float* __restrict__ bias, float* __restrict__ C,
             int M_, int N_, int K_) {
    extern __shared__ float smf[];
    const uint32_t smb = smem_u32(smf);

    const int tid = threadIdx.x, w = tid >> 5, lane = tid & 31;
    const int wm = w >> 2, wn = w & 3;
    const int g = lane >> 2, tg = lane & 3;
    const int row0 = blockIdx.y * 128, col0 = blockIdx.x * 128;

    const uint32_t X = (uint32_t)((lane & 7) << 2);
    const uint32_t aRow = (uint32_t)(wm * 64 + (lane & 15)) * 128;
    const uint32_t aCb  = (uint32_t)((lane >> 4) << 2);
    const uint32_t bRow = (uint32_t)(wn * 32 + (lane & 7)) * 128;
    const uint32_t bCb  = (uint32_t)(((lane >> 3) & 1) << 2);

    float acc[4][4][4];
#pragma unroll
    for (int mi = 0; mi < 4; mi++)
#pragma unroll
        for (int ni = 0; ni < 4; ni++)
#pragma unroll
            for (int c = 0; c < 4; c++) acc[mi][ni][c] = 0.f;

    const int T = K_ >> 5;

    auto load_tile = [&](int t, int buf) {
        const int k0g = t << 5;
        const uint32_t ab = smb + (uint32_t)buf * 32768u;
        const uint32_t bb = ab + 16384u;
#pragma unroll
        for (int it = 0; it < 4; it++) {
            int idx = it * 256 + tid;
            int r = idx >> 3, j = idx & 7;
            uint32_t doff = (uint32_t)swz(r, j * 4) * 4;
            cp16(ab + doff, &A [(size_t)(row0 + r) * K_ + k0g + j * 4]);
            cp16(bb + doff, &Bt[(size_t)(col0 + r) * K_ + k0g + j * 4]);
        }
        CP_COMMIT();
    };

    // prologue: stages 0 and 1 in flight
    load_tile(0, 0);
    load_tile(1, 1);

    int bi = 0;                 // buffer index of tile t (rotates 0,1,2)
    for (int t = 0; t < T; t++) {
        // issue t+2 into the buffer consumed at t-1 (safe: iteration t-1 ended
        // with a syncthreads after compute), then wait until tile t is resident.
        if (t + 2 < T) {
            int b2 = bi + 2; if (b2 >= 3) b2 -= 3;
            load_tile(t + 2, b2);
            asm volatile("cp.async.wait_group 2;" ::: "memory");
        } else if (t + 1 < T) {
            asm volatile("cp.async.wait_group 1;" ::: "memory");
        } else {
            asm volatile("cp.async.wait_group 0;" ::: "memory");
        }
        __syncthreads();

        const uint32_t abuf = smb + (uint32_t)bi * 32768u;
        const uint32_t bbuf = abuf + 16384u;

#pragma unroll
        for (int ks = 0; ks < 4; ks++) {
            const uint32_t k0 = (uint32_t)(ks * 8);
            uint32_t af[4][4];
#pragma unroll
            for (int mi = 0; mi < 4; mi++) {
                uint32_t addr = abuf + aRow + (uint32_t)(mi * 2048) + (((k0 + aCb) ^ X) << 2);
                ldsm_x4(af[mi][0], af[mi][1], af[mi][2], af[mi][3], addr);
            }
            uint32_t bf[4][2];
#pragma unroll
            for (int ni = 0; ni < 4; ni++) {
                uint32_t addr = bbuf + bRow + (uint32_t)(ni * 1024) + (((k0 + bCb) ^ X) << 2);
                ldsm_x2(bf[ni][0], bf[ni][1], addr);
            }
#pragma unroll
            for (int mi = 0; mi < 4; mi++) {
#pragma unroll
                for (int q = 0; q < 4; q++)
                    af[mi][q] = __float_as_uint(rn_tf32(__uint_as_float(af[mi][q])));
            }
#pragma unroll
            for (int mi = 0; mi < 4; mi++)
#pragma unroll
                for (int ni = 0; ni < 4; ni++)
                    mma_tf32(acc[mi][ni][0], acc[mi][ni][1], acc[mi][ni][2], acc[mi][ni][3],
                             af[mi][0], af[mi][1], af[mi][2], af[mi][3],
                             bf[ni][0], bf[ni][1]);
        }
        __syncthreads();
        if (++bi == 3) bi = 0;
    }

    // epilogue
#pragma unroll
    for (int mi = 0; mi < 4; mi++) {
#pragma unroll
        for (int ni = 0; ni < 4; ni++) {
            int row = row0 + wm * 64 + mi * 16 + g;
            int col = col0 + wn * 32 + ni * 8 + tg * 2;
            float b0 = bias[col], b1 = bias[col + 1];
#pragma unroll
            for (int hh = 0; hh < 2; hh++) {
                int r = row + hh * 8;
                float o0 = acc[mi][ni][hh * 2 + 0] + b0;
                float o1 = acc[mi][ni][hh * 2 + 1] + b1;
                if (ACT == 1) {
                    o0 = 0.5f * o0 * (1.f + erff(o0 * 0.70710678118654752440f));
                    o1 = 0.5f * o1 * (1.f + erff(o1 * 0.70710678118654752440f));
                }
                if (ACT == 2) { o0 = rn_tf32(o0); o1 = rn_tf32(o1); }
                float2 o = make_float2(o0, o1);
                *(float2*)&C[(size_t)r * N_ + col] = o;
            }
        }
    }
}

// ---------------- transpose + tf32-round: Wt[n][k] = rn(W[k][n]) ----------------
__global__ __launch_bounds__(256)
void transpose_rn(const float* __restrict__ W, float* __restrict__ Wt, int Kd, int Nd) {
    __shared__ float t[32][33];
    const int n0 = blockIdx.x * 32, k0 = blockIdx.y * 32;
    const int tx = threadIdx.x & 31, ty = (threadIdx.x >> 5) * 4;
#pragma unroll
    for (int i = 0; i < 4; i++)
        t[ty + i][tx] = W[(size_t)(k0 + ty + i) * Nd + n0 + tx];
    __syncthreads();
#pragma unroll
    for (int i = 0; i < 4; i++)
        Wt[(size_t)(n0 + ty + i) * Kd + k0 + tx] = rn_tf32(t[tx][ty + i]);
}

// ---------------- per-head V transpose: Vt[bh][dk][s] = V[b*S+s][h*64+dk] ----
__global__ __launch_bounds__(256)
void transpose_v(const float* __restrict__ V, float* __restrict__ Vt) {
    __shared__ float t[32][33];
    const int bh = blockIdx.z, b = bh >> 4, h = bh & 15;
    const int s0 = blockIdx.x * 32, d0 = blockIdx.y * 32;
    const int tx = threadIdx.x & 31, ty = (threadIdx.x >> 5) * 4;
#pragma unroll
    for (int i = 0; i < 4; i++)
        t[ty + i][tx] = V[(size_t)(b * Ss + s0 + ty + i) * Dd + h * 64 + d0 + tx];
    __syncthreads();
#pragma unroll
    for (int i = 0; i < 4; i++)
        Vt[((size_t)bh * 64 + d0 + ty + i) * Ss + s0 + tx] = t[tx][ty + i];
}

// ---------------- mma flash attention ----------------
// grid (B*H, S/128), 256 threads, 8 warps x 16 q-rows. K/V chunks of 64.
#define ATT_SM_BYTES (32768 * 4)

__global__ __launch_bounds__(256)
void attn_mma(const float* __restrict__ Q, const float* __restrict__ Kg,
              const float* __restrict__ Vt, const int* __restrict__ mask,
              const float* __restrict__ adj, float* __restrict__ Octx) {
    extern __shared__ float sa[];
    const uint32_t smb = smem_u32(sa);
    const int tid = threadIdx.x, w = tid >> 5, lane = tid & 31;
    const int bh = blockIdx.x, b = bh >> 4, h = bh & 15;
    const int q0 = blockIdx.y << 7;
    const int wq = w << 4;
    const int g = lane >> 2, tg = lane & 3;

    const uint32_t Ko[2] = {8192, 12288}, Vo[2] = {16384, 20480};
    const uint32_t Po = 24576 + (uint32_t)w * 1024;

    const uint32_t X   = (uint32_t)((lane & 7) << 2);
    const uint32_t aCb = (uint32_t)((lane >> 4) << 2);
    const uint32_t bCb = (uint32_t)(((lane >> 3) & 1) << 2);

    // Q tile [128 x 64] -> smem (swizzled)
#pragma unroll
    for (int it = 0; it < 8; it++) {
        int idx = it * 256 + tid;
        int r = idx >> 4, j = idx & 15;
        uint32_t doff = (uint32_t)(r * 64 + ((j * 4) ^ ((r & 7) << 2))) * 4;
        cp16(smb + doff, &Q[(size_t)(b * Ss + q0 + r) * Dd + h * 64 + j * 4]);
    }
    CP_COMMIT();

    auto load_kv = [&](int c, int buf) {
        const uint32_t kb = smb + Ko[buf] * 4;
        const uint32_t vb = smb + Vo[buf] * 4;
        const int kc = c << 6;
#pragma unroll
        for (int it = 0; it < 4; it++) {
            int idx = it * 256 + tid;
            int r = idx >> 4, j = idx & 15;
            uint32_t doff = (uint32_t)(r * 64 + ((j * 4) ^ ((r & 7) << 2))) * 4;
            cp16(kb + doff, &Kg[(size_t)(b * Ss + kc + r) * Dd + h * 64 + j * 4]);
            cp16(vb + doff, &Vt[((size_t)bh * 64 + r) * Ss + kc + j * 4]);
        }
        CP_COMMIT();
    };
    load_kv(0, 0);

    asm volatile("cp.async.wait_group 1;" ::: "memory");   // Q ready
    __syncthreads();

    // Q fragments (pre-rounded tf32 in the producing GEMM)
    uint32_t aq[8][4];
    {
        uint32_t qrow = smb + (uint32_t)(wq + (lane & 15)) * 256;
#pragma unroll
        for (int ks = 0; ks < 8; ks++)
            ldsm_x4(aq[ks][0], aq[ks][1], aq[ks][2], aq[ks][3],
                    qrow + ((((uint32_t)(ks * 8) + aCb) ^ X) << 2));
    }

    float m0 = -3.0e38f, m1 = -3.0e38f, l0 = 0.f, l1 = 0.f;
    float ao[8][4];
#pragma unroll
    for (int n = 0; n < 8; n++)
#pragma unroll
        for (int c = 0; c < 4; c++) ao[n][c] = 0.f;

    const float* adj0 = adj + ((size_t)(b * Ss + q0 + wq + g)) * Ss + 2 * tg;
    const int*   mb0  = mask + b * Ss + 2 * tg;

    for (int t = 0; t < 8; t++) {
        if (t + 1 < 8) {
            load_kv(t + 1, (t + 1) & 1);
            asm volatile("cp.async.wait_group 1;" ::: "memory");
        } else {
            asm volatile("cp.async.wait_group 0;" ::: "memory");
        }
        __syncthreads();

        const uint32_t kb = smb + Ko[t & 1] * 4;
        const uint32_t vb = smb + Vo[t & 1] * 4;

        // S = Q @ K^T
        float s[8][4];
#pragma unroll
        for (int n = 0; n < 8; n++)
#pragma unroll
            for (int c = 0; c < 4; c++) s[n][c] = 0.f;
#pragma unroll
        for (int ks = 0; ks < 8; ks++) {
            const uint32_t coff = ((((uint32_t)(ks * 8) + bCb) ^ X) << 2);
#pragma unroll
            for (int n = 0; n < 8; n++) {
                uint32_t b0, b1;
                ldsm_x2(b0, b1, kb + (uint32_t)(n * 8 + (lane & 7)) * 256 + coff);
                mma_tf32(s[n][0], s[n][1], s[n][2], s[n][3],
                         aq[ks][0], aq[ks][1], aq[ks][2], aq[ks][3], b0, b1);
            }
        }

        // mask + adj + scale; row max
        const int kc = t << 6;
        float mx0 = -3.0e38f, mx1 = -3.0e38f;
#pragma unroll
        for (int n = 0; n < 8; n++) {
            float2 a0 = *(const float2*)(adj0 + kc + n * 8);
            float2 a1 = *(const float2*)(adj0 + 8 * Ss + kc + n * 8);
            int2   mk = *(const int2*)  (mb0 + kc + n * 8);
            float p0 = (float)mk.x * -1e9f, p1 = (float)mk.y * -1e9f;
            s[n][0] = s[n][0] * 0.125f + p0 + a0.x;
            s[n][1] = s[n][1] * 0.125f + p1 + a0.y;
            s[n][2] = s[n][2] * 0.125f + p0 + a1.x;
            s[n][3] = s[n][3] * 0.125f + p1 + a1.y;
            mx0 = fmaxf(mx0, fmaxf(s[n][0], s[n][1]));
            mx1 = fmaxf(mx1, fmaxf(s[n][2], s[n][3]));
        }
        mx0 = fmaxf(mx0, __shfl_xor_sync(0xffffffffu, mx0, 1));
        mx0 = fmaxf(mx0, __shfl_xor_sync(0xffffffffu, mx0, 2));
        mx1 = fmaxf(mx1, __shfl_xor_sync(0xffffffffu, mx1, 1));
        mx1 = fmaxf(mx1, __shfl_xor_sync(0xffffffffu, mx1, 2));

        float mn0 = fmaxf(m0, mx0), mn1 = fmaxf(m1, mx1);
        float cor0 = expf(m0 - mn0), cor1 = expf(m1 - mn1);

        float ps0 = 0.f, ps1 = 0.f;
        const uint32_t xs = (uint32_t)(g << 2);
        float* Pw = sa + Po;
#pragma unroll
        for (int n = 0; n < 8; n++) {
            float p0 = rn_tf32(expf(s[n][0] - mn0));
            float p1 = rn_tf32(expf(s[n][1] - mn0));
            float p2 = rn_tf32(expf(s[n][2] - mn1));
            float p3 = rn_tf32(expf(s[n][3] - mn1));
            ps0 += p0 + p1; ps1 += p2 + p3;
            uint32_t cidx = ((uint32_t)(n * 8 + 2 * tg)) ^ xs;
            *(float2*)(Pw + g * 64 + cidx)       = make_float2(p0, p1);
            *(float2*)(Pw + (g + 8) * 64 + cidx) = make_float2(p2, p3);
        }
        ps0 += __shfl_xor_sync(0xffffffffu, ps0, 1);
        ps0 += __shfl_xor_sync(0xffffffffu, ps0, 2);
        ps1 += __shfl_xor_sync(0xffffffffu, ps1, 1);
        ps1 += __shfl_xor_sync(0xffffffffu, ps1, 2);
        l0 = l0 * cor0 + ps0; l1 = l1 * cor1 + ps1;
        m0 = mn0; m1 = mn1;
#pragma unroll
        for (int n = 0; n < 8; n++) {
            ao[n][0] *= cor0; ao[n][1] *= cor0;
            ao[n][2] *= cor1; ao[n][3] *= cor1;
        }
        __syncwarp();

        // O += P @ V   (Vt tile is [dk][key])
        const uint32_t prow = smb + Po * 4 + (uint32_t)(lane & 15) * 256;
#pragma unroll
        for (int ks = 0; ks < 8; ks++) {
            uint32_t ap0, ap1, ap2, ap3;
            ldsm_x4(ap0, ap1, ap2, ap3, prow + ((((uint32_t)(ks * 8) + aCb) ^ X) << 2));
            const uint32_t coff = ((((uint32_t)(ks * 8) + bCb) ^ X) << 2);
#pragma unroll
            for (int n = 0; n < 8; n++) {
                uint32_t b0, b1;
                ldsm_x2(b0, b1, vb + (uint32_t)(n * 8 + (lane & 7)) * 256 + coff);
                mma_tf32(ao[n][0], ao[n][1], ao[n][2], ao[n][3],
                         ap0, ap1, ap2, ap3, b0, b1);
            }
        }
        __syncthreads();
    }

    // epilogue
    const float inv0 = 1.0f / l0, inv1 = 1.0f / l1;
    const int qa = q0 + wq + g;
#pragma unroll
    for (int n = 0; n < 8; n++) {
        int col = h * 64 + n * 8 + 2 * tg;
        *(float2*)&Octx[(size_t)(b * Ss + qa) * Dd + col] =
            make_float2(ao[n][0] * inv0, ao[n][1] * inv0);
        *(float2*)&Octx[(size_t)(b * Ss + qa + 8) * Dd + col] =
            make_float2(ao[n][2] * inv1, ao[n][3] * inv1);
    }
}

// ---------------- fused residual add + LayerNorm (ddof=1, /(std+eps)) -------
__global__ __launch_bounds__(256)
void add_ln_kernel(const float* __restrict__ A, const float* __restrict__ Bv,
                   const float* __restrict__ gamma, const float* __restrict__ beta,
                   float* __restrict__ out) {
    const int row = blockIdx.x;
    const int tid = threadIdx.x;
    const size_t base = (size_t)row * 1024 + tid * 4;

    float4 a = *(const float4*)(A + base);
    float4 b = *(const float4*)(Bv + base);
    float v0 = a.x + b.x, v1 = a.y + b.y, v2 = a.z + b.z, v3 = a.w + b.w;

    __shared__ float red[8];
    __shared__ float s_stat;

    float s = v0 + v1 + v2 + v3;
#pragma unroll
    for (int o = 16; o >= 1; o >>= 1) s += __shfl_xor_sync(0xffffffffu, s, o);
    if ((tid & 31) == 0) red[tid >> 5] = s;
    __syncthreads();
    if (tid == 0) {
        float t = 0.f;
#pragma unroll
        for (int i = 0; i < 8; i++) t += red[i];
        s_stat = t * (1.0f / 1024.0f);
    }
    __syncthreads();
    const float mean = s_stat;

    float d0 = v0 - mean, d1 = v1 - mean, d2 = v2 - mean, d3 = v3 - mean;
    float q = d0 * d0 + d1 * d1 + d2 * d2 + d3 * d3;
#pragma unroll
    for (int o = 16; o >= 1; o >>= 1) q += __shfl_xor_sync(0xffffffffu, q, o);
    if ((tid & 31) == 0) red[tid >> 5] = q;
    __syncthreads();
    if (tid == 0) {
        float t = 0.f;
#pragma unroll
        for (int i = 0; i < 8; i++) t += red[i];
        float var = t * (1.0f / 1023.0f);        // ddof = 1
        s_stat = 1.0f / (sqrtf(var) + 1e-6f);    // 1 / (std + eps)
    }
    __syncthreads();
    const float rs = s_stat;

    float4 gm = *(const float4*)(gamma + tid * 4);
    float4 bt = *(const float4*)(beta  + tid * 4);
    float4 o;
    o.x = gm.x * d0 * rs + bt.x;
    o.y = gm.y * d1 * rs + bt.y;
    o.z = gm.z * d2 * rs + bt.z;
    o.w = gm.w * d3 * rs + bt.w;
    *(float4*)(out + base) = o;
}

// ---------------- launch ----------------
extern "C" void kernel_launch(void* const* d_in, const int* in_sizes, int n_in,
                              void* d_out, int out_size) {
    const float* x    = (const float*)d_in[0];
    const int*   mask = (const int*)  d_in[1];
    const float* adj  = (const float*)d_in[2];
    const float* Wq = (const float*)d_in[4],  *bq = (const float*)d_in[5];
    const float* Wk = (const float*)d_in[6],  *bk = (const float*)d_in[7];
    const float* Wv = (const float*)d_in[8],  *bv = (const float*)d_in[9];
    const float* Wo = (const float*)d_in[10], *bo = (const float*)d_in[11];
    const float* W1 = (const float*)d_in[12], *b1 = (const float*)d_in[13];
    const float* W2 = (const float*)d_in[14], *b2 = (const float*)d_in[15];
    const float* gamma = (const float*)d_in[16];
    const float* beta  = (const float*)d_in[17];
    float* out = (float*)d_out;

    float *q, *k, *v, *vt, *ctx, *t1, *o1, *ffn;
    float *wqt, *wkt, *wvt, *wot, *w1t, *w2t;
    cudaGetSymbolAddress((void**)&q,   g_q);
    cudaGetSymbolAddress((void**)&k,   g_k);
    cudaGetSymbolAddress((void**)&v,   g_v);
    cudaGetSymbolAddress((void**)&vt,  g_vt);
    cudaGetSymbolAddress((void**)&ctx, g_ctx);
    cudaGetSymbolAddress((void**)&t1,  g_t1);
    cudaGetSymbolAddress((void**)&o1,  g_o1);
    cudaGetSymbolAddress((void**)&ffn, g_ffn);
    cudaGetSymbolAddress((void**)&wqt, g_wqt);
    cudaGetSymbolAddress((void**)&wkt, g_wkt);
    cudaGetSymbolAddress((void**)&wvt, g_wvt);
    cudaGetSymbolAddress((void**)&wot, g_wot);
    cudaGetSymbolAddress((void**)&w1t, g_w1t);
    cudaGetSymbolAddress((void**)&w2t, g_w2t);

    cudaFuncSetAttribute(gemm_tc<0>, cudaFuncAttributeMaxDynamicSharedMemorySize, GSM_BYTES);
    cudaFuncSetAttribute(gemm_tc<1>, cudaFuncAttributeMaxDynamicSharedMemorySize, GSM_BYTES);
    cudaFuncSetAttribute(gemm_tc<2>, cudaFuncAttributeMaxDynamicSharedMemorySize, GSM_BYTES);
    cudaFuncSetAttribute(attn_mma, cudaFuncAttributeMaxDynamicSharedMemorySize, ATT_SM_BYTES);

    const dim3 blk(256);
    const dim3 tD(Dd / 32, Dd / 32);
    transpose_rn<<<tD, blk>>>(Wq, wqt, Dd, Dd);
    transpose_rn<<<tD, blk>>>(Wk, wkt, Dd, Dd);
    transpose_rn<<<tD, blk>>>(Wv, wvt, Dd, Dd);
    transpose_rn<<<tD, blk>>>(Wo, wot, Dd, Dd);
    transpose_rn<<<dim3(Ff / 32, Dd / 32), blk>>>(W1, w1t, Dd, Ff);
    transpose_rn<<<dim3(Dd / 32, Ff / 32), blk>>>(W2, w2t, Ff, Dd);

    const dim3 gD(Dd / 128, Mm / 128);   // (8, 128)
    const dim3 gF(Ff / 128, Mm / 128);   // (32, 128)

    // 1-3. Q/K/V projections (tf32-rounded outputs for the mma attention)
    gemm_tc<2><<<gD, blk, GSM_BYTES>>>(x, wqt, bq, q, Mm, Dd, Dd);
    gemm_tc<2><<<gD, blk, GSM_BYTES>>>(x, wkt, bk, k, Mm, Dd, Dd);
    gemm_tc<2><<<gD, blk, GSM_BYTES>>>(x, wvt, bv, v, Mm, Dd, Dd);

    // 3b. per-head V transpose
    transpose_v<<<dim3(Ss / 32, 2, Bb * Hh), blk>>>(v, vt);

    // 4. attention (tensor cores)
    attn_mma<<<dim3(Bb * Hh, Ss / 128), blk, ATT_SM_BYTES>>>(q, k, vt, mask, adj, ctx);

    // 5. output projection
    gemm_tc<0><<<gD, blk, GSM_BYTES>>>(ctx, wot, bo, t1, Mm, Dd, Dd);

    // 6. residual + LN -> out1
    add_ln_kernel<<<Mm, blk>>>(x, t1, gamma, beta, o1);

    // 7. FFN1 + GELU
    gemm_tc<1><<<gF, blk, GSM_BYTES>>>(o1, w1t, b1, ffn, Mm, Ff, Dd);

    // 8. FFN2
    gemm_tc<0><<<gD, blk, GSM_BYTES>>>(ffn, w2t, b2, t1, Mm, Dd, Ff);

    // 9. residual + LN -> out
    add_ln_kernel<<<Mm, blk>>>(o1, t1, gamma, beta, out);
}